// round 7
// baseline (speedup 1.0000x reference)
#include <cuda_runtime.h>

// ---------------- problem constants ----------------
#define KB     8
#define KC     64
#define KHW    76800      // 240*320
#define KCL    10
#define ALPHA_C   0.02f
#define DELTA_C   0.5f
#define MINW_C    50.0f

// pass-1 tiling: (b, chunk, cgrp) -> 960 blocks of 1280 pixels, 32 channels
#define CHUNKS1 60
#define PX1     (KHW / CHUNKS1)     // 1280
#define NBLK1   (KB * CHUNKS1 * 2)  // 960

// pass-2 tiling: 1200 blocks of 512 pixels (128 thr * 4 px)
#define CHUNKS3 150
#define PX3     (KHW / CHUNKS3)     // 512
#define NBLK3   (KB * CHUNKS3)      // 1200

// ---------------- device scratch (zero-init .bss; launches restore) -------
__device__ float g_sums[KB][KC][KCL];     // K1 accumulates; K1-finalize zeroes
__device__ float g_cnt[KB][KCL];          // K1 accumulates; K1-finalize zeroes
__device__ float g_means[KB][KCL][KC];    // K1-finalize overwrites
__device__ float g_inter;                 // K1-finalize overwrites
__device__ float g_d2[KB * KCL];          // K3 accumulates; K3-finalize zeroes
__device__ float g_nk[KB * KCL];          // K3 accumulates; K3-finalize zeroes
__device__ unsigned int g_tick1;          // K1 ticket; finalize zeroes
__device__ unsigned int g_tick3;          // K3 ticket; finalize zeroes

// ---------------- f32x2 helpers ----------------
__device__ __forceinline__ unsigned long long pack2(float lo, float hi) {
    unsigned long long r;
    asm("mov.b64 %0, {%1, %2};" : "=l"(r) : "f"(lo), "f"(hi));
    return r;
}
__device__ __forceinline__ void unpack2(unsigned long long v, float& lo, float& hi) {
    asm("mov.b64 {%0, %1}, %2;" : "=f"(lo), "=f"(hi) : "l"(v));
}
__device__ __forceinline__ void ffma2(unsigned long long& d,
                                      unsigned long long a, unsigned long long b) {
    asm("fma.rn.f32x2 %0, %1, %2, %0;" : "+l"(d) : "l"(a), "l"(b));
}

// =====================================================================
// K1: per-cluster channel sums + counts; fused finalize computes
// normalized means AND the inter-cluster hinge loss.
// 8 warps/block; warp owns 4 channels; lane owns a pixel QUAD (float4).
// Front-batched burst: 4x independent LDG.128 (2KB/warp in flight).
// =====================================================================
__global__ __launch_bounds__(256, 3) void k1_sums(const float* __restrict__ x,
                                                  const int* __restrict__ cmask)
{
    __shared__ unsigned char s_cm[PX1];
    __shared__ int s_cnt[KCL];
    __shared__ unsigned long long s_tbl[KCL][5];
    __shared__ unsigned int s_last;
    __shared__ float s_means[KB * KCL * 65];   // finalize only
    __shared__ float s_r[8];

    const int bid   = blockIdx.x;
    const int b     = bid / (CHUNKS1 * 2);
    const int r0    = bid % (CHUNKS1 * 2);
    const int cgrp  = r0 & 1;
    const int pbase = (r0 >> 1) * PX1;
    const int tid   = threadIdx.x;
    const int lane  = tid & 31;
    const int warp  = tid >> 5;

    if (tid < KCL) s_cnt[tid] = 0;
    // one-hot pair LUT: tbl[v][kk] = ( v==2kk , v==2kk+1 )
    if (tid < KCL * 5) {
        const int v = tid / 5, kk = tid % 5;
        s_tbl[v][kk] = pack2((v == 2 * kk) ? 1.0f : 0.0f,
                             (v == 2 * kk + 1) ? 1.0f : 0.0f);
    }

    // stage masks (+ counts only from channel-group 0)
    const int* cmb = cmask + b * KHW + pbase;
    if (cgrp == 0) {
        int cnt[KCL];
#pragma unroll
        for (int k = 0; k < KCL; k++) cnt[k] = 0;
#pragma unroll
        for (int i = 0; i < PX1 / 256; i++) {
            const int p = tid + i * 256;
            const int v = cmb[p];
            s_cm[p] = (unsigned char)v;
#pragma unroll
            for (int k = 0; k < KCL; k++) cnt[k] += (v == k);
        }
        __syncthreads();
#pragma unroll
        for (int k = 0; k < KCL; k++) {
            int v = cnt[k];
#pragma unroll
            for (int o = 16; o; o >>= 1) v += __shfl_xor_sync(0xffffffffu, v, o);
            if (lane == 0) atomicAdd(&s_cnt[k], v);
        }
        __syncthreads();
        if (tid < KCL) atomicAdd(&g_cnt[b][tid], (float)s_cnt[tid]);
    } else {
#pragma unroll
        for (int i = 0; i < PX1 / 256; i++) {
            const int p = tid + i * 256;
            s_cm[p] = (unsigned char)cmb[p];
        }
        __syncthreads();
    }

    // ---- main accumulation: warp's 4 channels, lane owns pixel quads ----
    const int c0 = cgrp * 32 + warp * 4;
    const float* xp = x + ((size_t)(b * KC + c0)) * KHW + pbase;

    unsigned long long acc[4][5];
#pragma unroll
    for (int j = 0; j < 4; j++)
#pragma unroll
        for (int kk = 0; kk < 5; kk++) acc[j][kk] = 0ull;

    for (int it = 0; it < PX1 / 128; it++) {
        const int p = 4 * lane + it * 128;

        // ---- load burst: 4 independent LDG.128 + 1 LDS.32 ----
        float4 xv[4];
#pragma unroll
        for (int j = 0; j < 4; j++)
            xv[j] = *(const float4*)(xp + (size_t)j * KHW + p);
        const unsigned int cmq = *(const unsigned int*)(s_cm + p);

        // ---- compute phase: 4 pixels of the quad ----
#pragma unroll
        for (int qq = 0; qq < 4; qq++) {
            const int cv = (cmq >> (8 * qq)) & 0xffu;
            unsigned long long m2[5];
#pragma unroll
            for (int kk = 0; kk < 5; kk++) m2[kk] = s_tbl[cv][kk];
            const float v0 = (qq == 0) ? xv[0].x : (qq == 1) ? xv[0].y : (qq == 2) ? xv[0].z : xv[0].w;
            const float v1 = (qq == 0) ? xv[1].x : (qq == 1) ? xv[1].y : (qq == 2) ? xv[1].z : xv[1].w;
            const float v2 = (qq == 0) ? xv[2].x : (qq == 1) ? xv[2].y : (qq == 2) ? xv[2].z : xv[2].w;
            const float v3 = (qq == 0) ? xv[3].x : (qq == 1) ? xv[3].y : (qq == 2) ? xv[3].z : xv[3].w;
            const unsigned long long x0 = pack2(v0, v0);
            const unsigned long long x1 = pack2(v1, v1);
            const unsigned long long x2 = pack2(v2, v2);
            const unsigned long long x3 = pack2(v3, v3);
#pragma unroll
            for (int kk = 0; kk < 5; kk++) {
                ffma2(acc[0][kk], x0, m2[kk]);
                ffma2(acc[1][kk], x1, m2[kk]);
                ffma2(acc[2][kk], x2, m2[kk]);
                ffma2(acc[3][kk], x3, m2[kk]);
            }
        }
    }

    // warp butterfly reduce, lane0 atomics into global sums
#pragma unroll
    for (int j = 0; j < 4; j++) {
#pragma unroll
        for (int kk = 0; kk < 5; kk++) {
            float lo, hi;
            unpack2(acc[j][kk], lo, hi);
#pragma unroll
            for (int o = 16; o; o >>= 1) {
                lo += __shfl_xor_sync(0xffffffffu, lo, o);
                hi += __shfl_xor_sync(0xffffffffu, hi, o);
            }
            if (lane == 0) {
                atomicAdd(&g_sums[b][c0 + j][2 * kk],     lo);
                atomicAdd(&g_sums[b][c0 + j][2 * kk + 1], hi);
            }
        }
    }

    // ---- ticket: last block computes means + inter loss ----
    __threadfence();
    __syncthreads();
    if (tid == 0)
        s_last = (atomicAdd(&g_tick1, 1u) == (unsigned)(NBLK1 - 1)) ? 1u : 0u;
    __syncthreads();
    if (!s_last) return;
    __threadfence();

    // means: 80 rows (b,k); warp per row stripe, lanes cover c and c+32
    for (int row = warp; row < KB * KCL; row += 8) {
        const int bb = row / KCL;
        const int kk = row % KCL;
        const float cntv = g_cnt[bb][kk];
        const float m0 = g_sums[bb][lane][kk]      / (cntv + 1e-10f);
        const float m1 = g_sums[bb][lane + 32][kk] / (cntv + 1e-10f);
        float sq = m0 * m0 + m1 * m1;
#pragma unroll
        for (int o = 16; o; o >>= 1) sq += __shfl_xor_sync(0xffffffffu, sq, o);
        const float inv = 1.0f / fmaxf(sqrtf(sq), 1e-12f);
        const float n0 = m0 * inv, n1 = m1 * inv;
        g_means[bb][kk][lane]      = n0;
        g_means[bb][kk][lane + 32] = n1;
        s_means[row * 65 + lane]      = n0;
        s_means[row * 65 + lane + 32] = n1;
        // reset for next launch
        g_sums[bb][lane][kk]      = 0.0f;
        g_sums[bb][lane + 32][kk] = 0.0f;
        if (lane == 0) g_cnt[bb][kk] = 0.0f;
    }
    __syncthreads();

    // inter loss: warp-per-ordered-pair (720 pairs / 8 warps), lane0 accum
    float acc_inter = 0.f;
    for (int pr = warp; pr < KB * KCL * (KCL - 1); pr += 8) {
        const int bb = pr / 90;
        const int r  = pr % 90;
        const int k  = r / 9;
        int l = r % 9; if (l >= k) l++;
        const float* mk = &s_means[(bb * KCL + k) * 65];
        const float* ml = &s_means[(bb * KCL + l) * 65];
        float dv = mk[lane] * ml[lane] + mk[lane + 32] * ml[lane + 32];
#pragma unroll
        for (int o = 16; o; o >>= 1) dv += __shfl_xor_sync(0xffffffffu, dv, o);
        const float h = fmaxf(DELTA_C - 0.5f * (1.0f - dv), 0.0f);
        if (lane == 0) acc_inter += h * h;
    }
    if (lane == 0) s_r[warp] = acc_inter;
    __syncthreads();
    if (tid == 0) {
        float t = 0.f;
#pragma unroll
        for (int w = 0; w < 8; w++) t += s_r[w];
        g_inter = t;
        g_tick1 = 0u;
    }
}

// =====================================================================
// K3: second pass, 4 px/thread, channels in 8-wide windows with an
// explicit 8x LDG.128 load burst (MLP_p1 = 8). Small smem (~3 KB).
// Ticket-last-block finalize: intra + combine with g_inter.
// =====================================================================
__global__ __launch_bounds__(128, 8) void k3_intra(const float* __restrict__ x,
                                                   const int* __restrict__ cmask,
                                                   float* __restrict__ out)
{
    __shared__ float msh[KCL * 65];
    __shared__ float s_d2[KCL];
    __shared__ float s_nk[KCL];
    __shared__ unsigned int s_last;

    const int bid   = blockIdx.x;
    const int b     = bid / CHUNKS3;
    const int pbase = (bid % CHUNKS3) * PX3;
    const int tid   = threadIdx.x;
    const int lane  = tid & 31;
    const int warp  = tid >> 5;

#pragma unroll
    for (int i = 0; i < 5; i++) {
        const int idx = tid + i * 128;
        msh[(idx >> 6) * 65 + (idx & 63)] = ((const float*)g_means)[b * KCL * KC + idx];
    }
    if (tid < KCL) { s_d2[tid] = 0.f; s_nk[tid] = 0.f; }
    __syncthreads();

    const int p0 = pbase + tid * 4;
    const int4 cm4 = *(const int4*)(cmask + b * KHW + p0);
    const float* xb = x + (size_t)b * KC * KHW + p0;

    const int kk4[4] = { cm4.x, cm4.y, cm4.z, cm4.w };
    const float* mp0 = &msh[cm4.x * 65];
    const float* mp1 = &msh[cm4.y * 65];
    const float* mp2 = &msh[cm4.z * 65];
    const float* mp3 = &msh[cm4.w * 65];

    float d0 = 0.f, d1 = 0.f, d2 = 0.f, d3 = 0.f;

#pragma unroll
    for (int w = 0; w < KC / 8; w++) {
        // ---- load burst: 8 channels in flight ----
        float4 buf[8];
#pragma unroll
        for (int cc = 0; cc < 8; cc++)
            buf[cc] = *(const float4*)(xb + (size_t)(w * 8 + cc) * KHW);
        // ---- compute phase ----
#pragma unroll
        for (int cc = 0; cc < 8; cc++) {
            const int c = w * 8 + cc;
            d0 = fmaf(buf[cc].x, mp0[c], d0);
            d1 = fmaf(buf[cc].y, mp1[c], d1);
            d2 = fmaf(buf[cc].z, mp2[c], d2);
            d3 = fmaf(buf[cc].w, mp3[c], d3);
        }
    }

    const float dots[4] = { d0, d1, d2, d3 };
#pragma unroll
    for (int i = 0; i < 4; i++) {
        const float dd = 0.5f * (1.0f - dots[i]);
        atomicAdd(&s_d2[kk4[i]], dd * dd);
        if (dd > ALPHA_C) atomicAdd(&s_nk[kk4[i]], 1.0f);
    }
    __syncthreads();
    if (tid < KCL) {
        atomicAdd(&g_d2[b * KCL + tid], s_d2[tid]);
        atomicAdd(&g_nk[b * KCL + tid], s_nk[tid]);
    }

    // ---- ticket: last block finalizes ----
    __threadfence();
    __syncthreads();
    if (tid == 0)
        s_last = (atomicAdd(&g_tick3, 1u) == (unsigned)(NBLK3 - 1)) ? 1u : 0u;
    __syncthreads();
    if (!s_last) return;
    __threadfence();

    // intra finalize + resets (80 values)
    float acc_intra = 0.f, acc_ind = 0.f;
    if (tid < KB * KCL) {
        const float nk = g_nk[tid];
        acc_intra = g_d2[tid] / (fmaxf(nk, MINW_C) * (float)KCL);
        acc_ind   = nk;
        g_nk[tid] = 0.f;
        g_d2[tid] = 0.f;
    }

    float v1 = acc_intra, v2 = acc_ind;
#pragma unroll
    for (int o = 16; o; o >>= 1) {
        v1 += __shfl_xor_sync(0xffffffffu, v1, o);
        v2 += __shfl_xor_sync(0xffffffffu, v2, o);
    }
    __shared__ float s_r1[4], s_r2[4];
    if (lane == 0) { s_r1[warp] = v1; s_r2[warp] = v2; }
    __syncthreads();
    if (tid == 0) {
        float t1 = 0.f, t2 = 0.f;
#pragma unroll
        for (int w = 0; w < 4; w++) { t1 += s_r1[w]; t2 += s_r2[w]; }
        const float inter_loss = g_inter / ((float)(KCL * (KCL - 1) / 2) * (float)KB);
        const float intra_loss = (t2 > 0.f) ? (t1 / (float)KB) : 0.f;
        out[0] = intra_loss + inter_loss;
        out[1] = intra_loss;
        out[2] = inter_loss;
        g_tick3 = 0u;
    }
}

// =====================================================================
extern "C" void kernel_launch(void* const* d_in, const int* in_sizes, int n_in,
                              void* d_out, int out_size)
{
    const float* x   = (const float*)d_in[0];
    const int*   cm  = (const int*)d_in[1];
    float*       out = (float*)d_out;

    k1_sums<<<NBLK1, 256>>>(x, cm);
    k3_intra<<<NBLK3, 128>>>(x, cm, out);
}

// round 8
// speedup vs baseline: 1.1420x; 1.1420x over previous
#include <cuda_runtime.h>

// ---------------- problem constants ----------------
#define KB     8
#define KC     64
#define KHW    76800      // 240*320
#define KCL    10
#define ALPHA_C   0.02f
#define DELTA_C   0.5f
#define MINW_C    50.0f

// pass-1 tiling: (b, chunk, cgrp) -> 960 blocks of 1280 pixels, 32 channels
#define CHUNKS1 60
#define PX1     (KHW / CHUNKS1)     // 1280
#define NBLK1   (KB * CHUNKS1 * 2)  // 960

// pass-2 tiling: 1200 blocks of 512 pixels (128 thr * 4 px)
#define CHUNKS3 150
#define PX3     (KHW / CHUNKS3)     // 512
#define NBLK3   (KB * CHUNKS3)      // 1200

// ---------------- device scratch (zero-init .bss; launches restore) -------
__device__ float g_sums[KB][KC][KCL];     // K1 accumulates; K1-finalize zeroes
__device__ float g_cnt[KB][KCL];          // K1 accumulates; K1-finalize zeroes
__device__ float g_means[KB][KCL][KC];    // K1-finalize overwrites
__device__ float g_inter;                 // K1-finalize overwrites
__device__ float g_d2[KB * KCL];          // K3 accumulates; K3-finalize zeroes
__device__ float g_nk[KB * KCL];          // K3 accumulates; K3-finalize zeroes
__device__ unsigned int g_tick1;          // K1 ticket; finalize zeroes
__device__ unsigned int g_tick3;          // K3 ticket; finalize zeroes

// =====================================================================
// K1: per-cluster channel sums + counts via warp-private smem bins.
// 8 warps/block; warp owns 4 channels; lane owns a pixel QUAD (float4).
// Bin layout s_acc[warp][k*128 + j*32 + lane] -> bank==lane: NO conflicts
// for any cluster pattern. Per element: LDS.32 + FADD + STS.32.
// Fused finalize: normalized means + inter hinge loss (bins re-used as
// the means staging buffer).
// =====================================================================
__global__ __launch_bounds__(256, 4) void k1_sums(const float* __restrict__ x,
                                                  const int* __restrict__ cmask)
{
    __shared__ unsigned char s_cm[PX1];
    __shared__ int s_cnt[KCL];
    __shared__ float s_acc[8][KCL * 4 * 32];   // 8 warps x 1280 floats = 40 KB
    __shared__ unsigned int s_last;
    __shared__ float s_r[8];

    const int bid   = blockIdx.x;
    const int b     = bid / (CHUNKS1 * 2);
    const int r0    = bid % (CHUNKS1 * 2);
    const int cgrp  = r0 & 1;
    const int pbase = (r0 >> 1) * PX1;
    const int tid   = threadIdx.x;
    const int lane  = tid & 31;
    const int warp  = tid >> 5;

    if (tid < KCL) s_cnt[tid] = 0;

    // zero this warp's bins (warp-private: no cross-warp sync needed)
    float* wacc = s_acc[warp];
#pragma unroll
    for (int i = 0; i < (KCL * 4 * 32) / 32; i++) wacc[i * 32 + lane] = 0.f;

    // stage masks (+ counts only from channel-group 0)
    const int* cmb = cmask + b * KHW + pbase;
    if (cgrp == 0) {
        int cnt[KCL];
#pragma unroll
        for (int k = 0; k < KCL; k++) cnt[k] = 0;
#pragma unroll
        for (int i = 0; i < PX1 / 256; i++) {
            const int p = tid + i * 256;
            const int v = cmb[p];
            s_cm[p] = (unsigned char)v;
#pragma unroll
            for (int k = 0; k < KCL; k++) cnt[k] += (v == k);
        }
        __syncthreads();
#pragma unroll
        for (int k = 0; k < KCL; k++) {
            int v = cnt[k];
#pragma unroll
            for (int o = 16; o; o >>= 1) v += __shfl_xor_sync(0xffffffffu, v, o);
            if (lane == 0) atomicAdd(&s_cnt[k], v);
        }
        __syncthreads();
        if (tid < KCL) atomicAdd(&g_cnt[b][tid], (float)s_cnt[tid]);
    } else {
#pragma unroll
        for (int i = 0; i < PX1 / 256; i++) {
            const int p = tid + i * 256;
            s_cm[p] = (unsigned char)cmb[p];
        }
        __syncthreads();
    }

    // ---- main accumulation: warp's 4 channels, lane owns pixel quads ----
    const int c0 = cgrp * 32 + warp * 4;
    const float* xp = x + ((size_t)(b * KC + c0)) * KHW + pbase;

    for (int it = 0; it < PX1 / 128; it++) {
        const int p = 4 * lane + it * 128;

        // ---- load burst: 4 independent LDG.128 + 1 LDS.32 ----
        const float4 x0 = *(const float4*)(xp + p);
        const float4 x1 = *(const float4*)(xp + (size_t)KHW + p);
        const float4 x2 = *(const float4*)(xp + (size_t)2 * KHW + p);
        const float4 x3 = *(const float4*)(xp + (size_t)3 * KHW + p);
        const unsigned int cmq = *(const unsigned int*)(s_cm + p);

        // ---- scatter phase: 4 pixels x 4 channels ----
        {
            float* a = wacc + (cmq & 0xffu) * 128 + lane;
            a[0] += x0.x; a[32] += x1.x; a[64] += x2.x; a[96] += x3.x;
        }
        {
            float* a = wacc + ((cmq >> 8) & 0xffu) * 128 + lane;
            a[0] += x0.y; a[32] += x1.y; a[64] += x2.y; a[96] += x3.y;
        }
        {
            float* a = wacc + ((cmq >> 16) & 0xffu) * 128 + lane;
            a[0] += x0.z; a[32] += x1.z; a[64] += x2.z; a[96] += x3.z;
        }
        {
            float* a = wacc + (cmq >> 24) * 128 + lane;
            a[0] += x0.w; a[32] += x1.w; a[64] += x2.w; a[96] += x3.w;
        }
    }

    // ---- per-warp reduce of bins -> global atomics ----
#pragma unroll
    for (int r = 0; r < KCL * 4; r++) {
        float v = wacc[r * 32 + lane];
#pragma unroll
        for (int o = 16; o; o >>= 1) v += __shfl_xor_sync(0xffffffffu, v, o);
        if (lane == 0)
            atomicAdd(&g_sums[b][c0 + (r & 3)][r >> 2], v);
    }

    // ---- ticket: last block computes means + inter loss ----
    __threadfence();
    __syncthreads();
    if (tid == 0)
        s_last = (atomicAdd(&g_tick1, 1u) == (unsigned)(NBLK1 - 1)) ? 1u : 0u;
    __syncthreads();
    if (!s_last) return;
    __threadfence();

    // bins are dead now; alias them as the means staging buffer (80x65 floats)
    float* s_means = &s_acc[0][0];

    // means: 80 rows (b,k); warp per row stripe, lanes cover c and c+32
    for (int row = warp; row < KB * KCL; row += 8) {
        const int bb = row / KCL;
        const int kk = row % KCL;
        const float cntv = g_cnt[bb][kk];
        const float m0 = g_sums[bb][lane][kk]      / (cntv + 1e-10f);
        const float m1 = g_sums[bb][lane + 32][kk] / (cntv + 1e-10f);
        float sq = m0 * m0 + m1 * m1;
#pragma unroll
        for (int o = 16; o; o >>= 1) sq += __shfl_xor_sync(0xffffffffu, sq, o);
        const float inv = 1.0f / fmaxf(sqrtf(sq), 1e-12f);
        const float n0 = m0 * inv, n1 = m1 * inv;
        g_means[bb][kk][lane]      = n0;
        g_means[bb][kk][lane + 32] = n1;
        s_means[row * 65 + lane]      = n0;
        s_means[row * 65 + lane + 32] = n1;
        // reset for next launch
        g_sums[bb][lane][kk]      = 0.0f;
        g_sums[bb][lane + 32][kk] = 0.0f;
        if (lane == 0) g_cnt[bb][kk] = 0.0f;
    }
    __syncthreads();

    // inter loss: warp-per-ordered-pair (720 pairs / 8 warps), lane0 accum
    float acc_inter = 0.f;
    for (int pr = warp; pr < KB * KCL * (KCL - 1); pr += 8) {
        const int bb = pr / 90;
        const int r  = pr % 90;
        const int k  = r / 9;
        int l = r % 9; if (l >= k) l++;
        const float* mk = &s_means[(bb * KCL + k) * 65];
        const float* ml = &s_means[(bb * KCL + l) * 65];
        float dv = mk[lane] * ml[lane] + mk[lane + 32] * ml[lane + 32];
#pragma unroll
        for (int o = 16; o; o >>= 1) dv += __shfl_xor_sync(0xffffffffu, dv, o);
        const float h = fmaxf(DELTA_C - 0.5f * (1.0f - dv), 0.0f);
        if (lane == 0) acc_inter += h * h;
    }
    if (lane == 0) s_r[warp] = acc_inter;
    __syncthreads();
    if (tid == 0) {
        float t = 0.f;
#pragma unroll
        for (int w = 0; w < 8; w++) t += s_r[w];
        g_inter = t;
        g_tick1 = 0u;
    }
}

// =====================================================================
// K3: second pass, 4 px/thread, channels in 8-wide windows with an
// explicit 8x LDG.128 load burst. Small smem (~3 KB).
// Ticket-last-block finalize: intra + combine with g_inter.
// =====================================================================
__global__ __launch_bounds__(128, 8) void k3_intra(const float* __restrict__ x,
                                                   const int* __restrict__ cmask,
                                                   float* __restrict__ out)
{
    __shared__ float msh[KCL * 65];
    __shared__ float s_d2[KCL];
    __shared__ float s_nk[KCL];
    __shared__ unsigned int s_last;

    const int bid   = blockIdx.x;
    const int b     = bid / CHUNKS3;
    const int pbase = (bid % CHUNKS3) * PX3;
    const int tid   = threadIdx.x;
    const int lane  = tid & 31;
    const int warp  = tid >> 5;

#pragma unroll
    for (int i = 0; i < 5; i++) {
        const int idx = tid + i * 128;
        msh[(idx >> 6) * 65 + (idx & 63)] = ((const float*)g_means)[b * KCL * KC + idx];
    }
    if (tid < KCL) { s_d2[tid] = 0.f; s_nk[tid] = 0.f; }
    __syncthreads();

    const int p0 = pbase + tid * 4;
    const int4 cm4 = *(const int4*)(cmask + b * KHW + p0);
    const float* xb = x + (size_t)b * KC * KHW + p0;

    const int kk4[4] = { cm4.x, cm4.y, cm4.z, cm4.w };
    const float* mp0 = &msh[cm4.x * 65];
    const float* mp1 = &msh[cm4.y * 65];
    const float* mp2 = &msh[cm4.z * 65];
    const float* mp3 = &msh[cm4.w * 65];

    float d0 = 0.f, d1 = 0.f, d2 = 0.f, d3 = 0.f;

#pragma unroll
    for (int w = 0; w < KC / 8; w++) {
        // ---- load burst: 8 channels in flight ----
        float4 buf[8];
#pragma unroll
        for (int cc = 0; cc < 8; cc++)
            buf[cc] = *(const float4*)(xb + (size_t)(w * 8 + cc) * KHW);
        // ---- compute phase ----
#pragma unroll
        for (int cc = 0; cc < 8; cc++) {
            const int c = w * 8 + cc;
            d0 = fmaf(buf[cc].x, mp0[c], d0);
            d1 = fmaf(buf[cc].y, mp1[c], d1);
            d2 = fmaf(buf[cc].z, mp2[c], d2);
            d3 = fmaf(buf[cc].w, mp3[c], d3);
        }
    }

    const float dots[4] = { d0, d1, d2, d3 };
#pragma unroll
    for (int i = 0; i < 4; i++) {
        const float dd = 0.5f * (1.0f - dots[i]);
        atomicAdd(&s_d2[kk4[i]], dd * dd);
        if (dd > ALPHA_C) atomicAdd(&s_nk[kk4[i]], 1.0f);
    }
    __syncthreads();
    if (tid < KCL) {
        atomicAdd(&g_d2[b * KCL + tid], s_d2[tid]);
        atomicAdd(&g_nk[b * KCL + tid], s_nk[tid]);
    }

    // ---- ticket: last block finalizes ----
    __threadfence();
    __syncthreads();
    if (tid == 0)
        s_last = (atomicAdd(&g_tick3, 1u) == (unsigned)(NBLK3 - 1)) ? 1u : 0u;
    __syncthreads();
    if (!s_last) return;
    __threadfence();

    // intra finalize + resets (80 values)
    float acc_intra = 0.f, acc_ind = 0.f;
    if (tid < KB * KCL) {
        const float nk = g_nk[tid];
        acc_intra = g_d2[tid] / (fmaxf(nk, MINW_C) * (float)KCL);
        acc_ind   = nk;
        g_nk[tid] = 0.f;
        g_d2[tid] = 0.f;
    }

    float v1 = acc_intra, v2 = acc_ind;
#pragma unroll
    for (int o = 16; o; o >>= 1) {
        v1 += __shfl_xor_sync(0xffffffffu, v1, o);
        v2 += __shfl_xor_sync(0xffffffffu, v2, o);
    }
    __shared__ float s_r1[4], s_r2[4];
    if (lane == 0) { s_r1[warp] = v1; s_r2[warp] = v2; }
    __syncthreads();
    if (tid == 0) {
        float t1 = 0.f, t2 = 0.f;
#pragma unroll
        for (int w = 0; w < 4; w++) { t1 += s_r1[w]; t2 += s_r2[w]; }
        const float inter_loss = g_inter / ((float)(KCL * (KCL - 1) / 2) * (float)KB);
        const float intra_loss = (t2 > 0.f) ? (t1 / (float)KB) : 0.f;
        out[0] = intra_loss + inter_loss;
        out[1] = intra_loss;
        out[2] = inter_loss;
        g_tick3 = 0u;
    }
}

// =====================================================================
extern "C" void kernel_launch(void* const* d_in, const int* in_sizes, int n_in,
                              void* d_out, int out_size)
{
    const float* x   = (const float*)d_in[0];
    const int*   cm  = (const int*)d_in[1];
    float*       out = (float*)d_out;

    k1_sums<<<NBLK1, 256>>>(x, cm);
    k3_intra<<<NBLK3, 128>>>(x, cm, out);
}